// round 2
// baseline (speedup 1.0000x reference)
#include <cuda_runtime.h>
#include <math.h>

typedef unsigned long long ull;

#define T_LEN 1024
#define B_DIM 256
#define D_DIM 64
#define H_DIM 128
#define BH (B_DIM * H_DIM)          // 32768
#define R_TOT (T_LEN * B_DIM)       // 262144

// Scratch: z[t][b][j] and h_all[t][b][j]
__device__ float g_z[(size_t)T_LEN * BH];
__device__ float g_h[(size_t)T_LEN * BH];

// ---------------- packed f32x2 helpers ----------------
__device__ __forceinline__ ull pk2(float lo, float hi) {
    ull r;
    asm("mov.b64 %0, {%1,%2};" : "=l"(r) : "r"(__float_as_uint(lo)), "r"(__float_as_uint(hi)));
    return r;
}
__device__ __forceinline__ float2 upk2(ull v) {
    unsigned int lo, hi;
    asm("mov.b64 {%0,%1}, %2;" : "=r"(lo), "=r"(hi) : "l"(v));
    return make_float2(__uint_as_float(lo), __uint_as_float(hi));
}
__device__ __forceinline__ void fma2(ull& d, ull a, ull b) {
    asm("fma.rn.f32x2 %0, %1, %2, %0;" : "+l"(d) : "l"(a), "l"(b));
}

// =====================================================================
// Phase 1: z = tanh(x @ W_x^T + b_x) @ W_ih^T + b_ih      [R_TOT, 128]
// 512 threads, 128 rows/CTA. Thread = 4x8 microtile (32x16 grid).
// =====================================================================
__global__ __launch_bounds__(512) void phase1_kernel(
    const float* __restrict__ x, const float* __restrict__ W_x,
    const float* __restrict__ b_x, const float* __restrict__ W_ih,
    const float* __restrict__ b_ih)
{
    extern __shared__ float sm[];
    float* WxT  = sm;            // [64][128]   WxT[d][m] = W_x[m][d]
    float* WihT = sm + 8192;     // [128][128]  WihT[m][j] = W_ih[j][m]
    float* xs   = sm + 24576;    // [128][64]
    float* fs   = sm + 32768;    // [128][128]
    float* bxs  = sm + 49152;    // [128]
    float* bihs = sm + 49280;    // [128]

    const int tid  = threadIdx.x;
    const int row0 = blockIdx.x * 128;

    for (int i = tid; i < 64 * 128; i += 512) {
        int d = i >> 7, m = i & 127;
        WxT[i] = W_x[m * 64 + d];
    }
    for (int i = tid; i < 128 * 128; i += 512) {
        int m = i >> 7, j = i & 127;
        WihT[i] = W_ih[j * 128 + m];
    }
    if (tid < 128) { bxs[tid] = b_x[tid]; bihs[tid] = b_ih[tid]; }

    const float4* xg  = (const float4*)(x + (size_t)row0 * 64);
    float4*       xs4 = (float4*)xs;
    for (int i = tid; i < 2048; i += 512) xs4[i] = xg[i];
    __syncthreads();

    const int tx = tid & 15, ty = tid >> 4;   // ty 0..31
    const int r0 = ty * 4, c0 = tx * 8;

    // ---- GEMM1: fs = tanh(xs @ WxT + b_x) ----
    ull acc[4][4];
    #pragma unroll
    for (int i = 0; i < 4; i++)
        #pragma unroll
        for (int jp = 0; jp < 4; jp++) acc[i][jp] = 0ull;

    #pragma unroll 4
    for (int d = 0; d < 64; ++d) {
        ull a[4];
        #pragma unroll
        for (int i = 0; i < 4; i++) {
            float av = xs[(r0 + i) * 64 + d];
            a[i] = pk2(av, av);
        }
        const ulonglong2* bp = (const ulonglong2*)(WxT + d * 128 + c0);
        ulonglong2 b0 = bp[0], b1 = bp[1];
        #pragma unroll
        for (int i = 0; i < 4; i++) {
            fma2(acc[i][0], a[i], b0.x);
            fma2(acc[i][1], a[i], b0.y);
            fma2(acc[i][2], a[i], b1.x);
            fma2(acc[i][3], a[i], b1.y);
        }
    }
    #pragma unroll
    for (int i = 0; i < 4; i++) {
        int r = r0 + i;
        #pragma unroll
        for (int jp = 0; jp < 4; jp++) {
            float2 v = upk2(acc[i][jp]);
            int c = c0 + jp * 2;
            fs[r * 128 + c]     = tanhf(v.x + bxs[c]);
            fs[r * 128 + c + 1] = tanhf(v.y + bxs[c + 1]);
        }
    }
    __syncthreads();

    // ---- GEMM2: z = fs @ WihT + b_ih ----
    #pragma unroll
    for (int i = 0; i < 4; i++)
        #pragma unroll
        for (int jp = 0; jp < 4; jp++) acc[i][jp] = 0ull;

    #pragma unroll 4
    for (int m = 0; m < 128; ++m) {
        ull a[4];
        #pragma unroll
        for (int i = 0; i < 4; i++) {
            float av = fs[(r0 + i) * 128 + m];
            a[i] = pk2(av, av);
        }
        const ulonglong2* bp = (const ulonglong2*)(WihT + m * 128 + c0);
        ulonglong2 b0 = bp[0], b1 = bp[1];
        #pragma unroll
        for (int i = 0; i < 4; i++) {
            fma2(acc[i][0], a[i], b0.x);
            fma2(acc[i][1], a[i], b0.y);
            fma2(acc[i][2], a[i], b1.x);
            fma2(acc[i][3], a[i], b1.y);
        }
    }
    #pragma unroll
    for (int i = 0; i < 4; i++) {
        int r = row0 + r0 + i;
        float2 v0 = upk2(acc[i][0]), v1 = upk2(acc[i][1]);
        float2 v2 = upk2(acc[i][2]), v3 = upk2(acc[i][3]);
        float4 o0 = make_float4(v0.x + bihs[c0],     v0.y + bihs[c0 + 1],
                                v1.x + bihs[c0 + 2], v1.y + bihs[c0 + 3]);
        float4 o1 = make_float4(v2.x + bihs[c0 + 4], v2.y + bihs[c0 + 5],
                                v3.x + bihs[c0 + 6], v3.y + bihs[c0 + 7]);
        float4* zp = (float4*)(g_z + (size_t)r * 128 + c0);
        zp[0] = o0; zp[1] = o1;
    }
}

// =====================================================================
// Phase 2: recurrence. One CTA per batch row b; thread j owns output j.
// z prefetched 4 iterations deep; double-buffered hs -> 1 barrier/step.
// =====================================================================
__global__ __launch_bounds__(128) void rnn_kernel(
    const float* __restrict__ W_hh, const float* __restrict__ b_hh)
{
    __shared__ __align__(16) float hs[2][128];

    const int b = blockIdx.x;
    const int j = threadIdx.x;

    ull w[64];
    const ulonglong2* w2 = (const ulonglong2*)(W_hh + j * 128);
    #pragma unroll
    for (int i = 0; i < 32; i++) {
        ulonglong2 v = w2[i];
        w[2 * i]     = v.x;
        w[2 * i + 1] = v.y;
    }
    const float bh = b_hh[j];

    hs[0][j] = 0.0f;
    g_h[(size_t)b * 128 + j] = 0.0f;                 // h_0 = 0

    const float* zp = g_z + (size_t)b * 128 + j;     // stride BH per t
    float z0 = zp[0];
    float z1 = zp[(size_t)1 * BH];
    float z2 = zp[(size_t)2 * BH];
    float z3 = zp[(size_t)3 * BH];
    __syncthreads();

    #pragma unroll 1
    for (int t = 0; t < T_LEN - 1; ++t) {
        float znew = 0.0f;
        if (t + 4 < T_LEN - 1) znew = __ldcg(zp + (size_t)(t + 4) * BH);

        const ulonglong2* h2 = (const ulonglong2*)hs[t & 1];
        ull a[8];
        #pragma unroll
        for (int i = 0; i < 8; i++) a[i] = 0ull;
        #pragma unroll
        for (int i = 0; i < 32; ++i) {
            ulonglong2 hv = h2[i];
            fma2(a[(2 * i) & 7],     hv.x, w[2 * i]);
            fma2(a[(2 * i + 1) & 7], hv.y, w[2 * i + 1]);
        }
        float2 f0 = upk2(a[0]), f1 = upk2(a[1]), f2 = upk2(a[2]), f3 = upk2(a[3]);
        float2 f4 = upk2(a[4]), f5 = upk2(a[5]), f6 = upk2(a[6]), f7 = upk2(a[7]);
        float s = (((f0.x + f0.y) + (f1.x + f1.y)) + ((f2.x + f2.y) + (f3.x + f3.y)))
                + (((f4.x + f4.y) + (f5.x + f5.y)) + ((f6.x + f6.y) + (f7.x + f7.y)));
        float hn = tanhf(s + z0 + bh);

        z0 = z1; z1 = z2; z2 = z3; z3 = znew;

        hs[(t + 1) & 1][j] = hn;
        g_h[(size_t)(t + 1) * BH + b * 128 + j] = hn;
        __syncthreads();
    }
}

// =====================================================================
// Phase 3: y = tanh(h_all @ W_h^T + b_h) @ W_g^T + b_g    [R_TOT, 64]
// 512 threads; GEMM1 microtile 4x8, GEMM2 microtile 4x4.
// =====================================================================
__global__ __launch_bounds__(512) void phase3_kernel(
    const float* __restrict__ W_h, const float* __restrict__ b_h,
    const float* __restrict__ W_g, const float* __restrict__ b_g,
    float* __restrict__ y)
{
    extern __shared__ float sm[];
    float* WhT = sm;             // [128][128]  WhT[m][j] = W_h[j][m]
    float* WgT = sm + 16384;     // [128][64]   WgT[j][d] = W_g[d][j]
    float* hb  = sm + 24576;     // [128][128]  h tile, reused for tanh(u)
    float* bhs = sm + 40960;     // [128]
    float* bgs = sm + 41088;     // [64]

    const int tid  = threadIdx.x;
    const int row0 = blockIdx.x * 128;

    for (int i = tid; i < 128 * 128; i += 512) {
        int m = i >> 7, j = i & 127;
        WhT[i] = W_h[j * 128 + m];
    }
    for (int i = tid; i < 128 * 64; i += 512) {
        int j = i >> 6, d = i & 63;
        WgT[i] = W_g[d * 128 + j];
    }
    if (tid < 128) bhs[tid] = b_h[tid];
    if (tid < 64)  bgs[tid] = b_g[tid];

    const float4* hg  = (const float4*)(g_h + (size_t)row0 * 128);
    float4*       hb4 = (float4*)hb;
    for (int i = tid; i < 4096; i += 512) hb4[i] = hg[i];
    __syncthreads();

    const int tx = tid & 15, ty = tid >> 4;
    const int r0 = ty * 4, c0 = tx * 8;

    // ---- GEMM1: u = tanh(hb @ WhT + b_h) ----
    ull acc[4][4];
    #pragma unroll
    for (int i = 0; i < 4; i++)
        #pragma unroll
        for (int jp = 0; jp < 4; jp++) acc[i][jp] = 0ull;

    #pragma unroll 4
    for (int m = 0; m < 128; ++m) {
        ull a[4];
        #pragma unroll
        for (int i = 0; i < 4; i++) {
            float av = hb[(r0 + i) * 128 + m];
            a[i] = pk2(av, av);
        }
        const ulonglong2* bp = (const ulonglong2*)(WhT + m * 128 + c0);
        ulonglong2 b0 = bp[0], b1 = bp[1];
        #pragma unroll
        for (int i = 0; i < 4; i++) {
            fma2(acc[i][0], a[i], b0.x);
            fma2(acc[i][1], a[i], b0.y);
            fma2(acc[i][2], a[i], b1.x);
            fma2(acc[i][3], a[i], b1.y);
        }
    }
    __syncthreads();   // all reads of hb done before in-place overwrite
    #pragma unroll
    for (int i = 0; i < 4; i++) {
        int r = r0 + i;
        #pragma unroll
        for (int jp = 0; jp < 4; jp++) {
            float2 v = upk2(acc[i][jp]);
            int c = c0 + jp * 2;
            hb[r * 128 + c]     = tanhf(v.x + bhs[c]);
            hb[r * 128 + c + 1] = tanhf(v.y + bhs[c + 1]);
        }
    }
    __syncthreads();

    // ---- GEMM2: y = u @ WgT + b_g  (64 output cols -> 4x4 microtile) ----
    const int c2 = tx * 4;
    ull ac2[4][2];
    #pragma unroll
    for (int i = 0; i < 4; i++) { ac2[i][0] = 0ull; ac2[i][1] = 0ull; }

    #pragma unroll 4
    for (int m = 0; m < 128; ++m) {
        ull a[4];
        #pragma unroll
        for (int i = 0; i < 4; i++) {
            float av = hb[(r0 + i) * 128 + m];
            a[i] = pk2(av, av);
        }
        const ulonglong2* bp = (const ulonglong2*)(WgT + m * 64 + c2);
        ulonglong2 bv = bp[0];
        #pragma unroll
        for (int i = 0; i < 4; i++) {
            fma2(ac2[i][0], a[i], bv.x);
            fma2(ac2[i][1], a[i], bv.y);
        }
    }
    #pragma unroll
    for (int i = 0; i < 4; i++) {
        int r = row0 + r0 + i;
        float2 v0 = upk2(ac2[i][0]), v1 = upk2(ac2[i][1]);
        float4 o = make_float4(v0.x + bgs[c2],     v0.y + bgs[c2 + 1],
                               v1.x + bgs[c2 + 2], v1.y + bgs[c2 + 3]);
        ((float4*)(y + (size_t)r * 64 + c2))[0] = o;
    }
}

// =====================================================================
extern "C" void kernel_launch(void* const* d_in, const int* in_sizes, int n_in,
                              void* d_out, int out_size)
{
    const float* x    = (const float*)d_in[0];
    const float* W_x  = (const float*)d_in[1];
    const float* b_x  = (const float*)d_in[2];
    const float* W_ih = (const float*)d_in[3];
    const float* b_ih = (const float*)d_in[4];
    const float* W_hh = (const float*)d_in[5];
    const float* b_hh = (const float*)d_in[6];
    const float* W_h  = (const float*)d_in[7];
    const float* b_h  = (const float*)d_in[8];
    const float* W_g  = (const float*)d_in[9];
    const float* b_g  = (const float*)d_in[10];
    float* y = (float*)d_out;

    cudaFuncSetAttribute(phase1_kernel, cudaFuncAttributeMaxDynamicSharedMemorySize, 49408 * 4);
    cudaFuncSetAttribute(phase3_kernel, cudaFuncAttributeMaxDynamicSharedMemorySize, 41152 * 4);

    phase1_kernel<<<R_TOT / 128, 512, 49408 * 4>>>(x, W_x, b_x, W_ih, b_ih);
    rnn_kernel<<<B_DIM, 128>>>(W_hh, b_hh);
    phase3_kernel<<<R_TOT / 128, 512, 41152 * 4>>>(W_h, b_h, W_g, b_g, y);
}

// round 4
// speedup vs baseline: 1.8882x; 1.8882x over previous
#include <cuda_runtime.h>
#include <cuda_bf16.h>
#include <math.h>
#include <stdint.h>

typedef unsigned long long ull;

#define T_LEN 1024
#define B_DIM 256
#define H_DIM 128
#define BH (B_DIM * H_DIM)          // 32768
#define R_TOT (T_LEN * B_DIM)       // 262144

__device__ float g_z[(size_t)T_LEN * BH];
__device__ float g_h[(size_t)T_LEN * BH];

// ---------------- helpers ----------------
__device__ __forceinline__ uint32_t smaddr(const void* p) {
    uint32_t a;
    asm("{ .reg .u64 t; cvta.to.shared.u64 t, %1; cvt.u32.u64 %0, t; }" : "=r"(a) : "l"(p));
    return a;
}
// pack two f32 -> bf16x2 word (low half = first arg)
__device__ __forceinline__ uint32_t cvt_bf2(float lo, float hi) {
    uint32_t r;
    asm("cvt.rn.bf16x2.f32 %0, %1, %2;" : "=r"(r) : "f"(hi), "f"(lo));
    return r;
}
__device__ __forceinline__ float lo2f(uint32_t w) { return __uint_as_float(w << 16); }
__device__ __forceinline__ float hi2f(uint32_t w) { return __uint_as_float(w & 0xFFFF0000u); }
__device__ __forceinline__ void split2(float vx, float vy, uint32_t& hi, uint32_t& lo) {
    hi = cvt_bf2(vx, vy);
    lo = cvt_bf2(vx - lo2f(hi), vy - hi2f(hi));
}

#define LDSM4(r0, r1, r2, r3, addr) \
    asm volatile("ldmatrix.sync.aligned.m8n8.x4.shared.b16 {%0,%1,%2,%3}, [%4];" \
                 : "=r"(r0), "=r"(r1), "=r"(r2), "=r"(r3) : "r"(addr))

__device__ __forceinline__ void mma16816(float* d, uint32_t a0, uint32_t a1, uint32_t a2, uint32_t a3,
                                         uint32_t b0, uint32_t b1) {
    asm volatile(
        "mma.sync.aligned.m16n8k16.row.col.f32.bf16.bf16.f32 "
        "{%0,%1,%2,%3}, {%4,%5,%6,%7}, {%8,%9}, {%0,%1,%2,%3};"
        : "+f"(d[0]), "+f"(d[1]), "+f"(d[2]), "+f"(d[3])
        : "r"(a0), "r"(a1), "r"(a2), "r"(a3), "r"(b0), "r"(b1));
}

// Warp-level split-bf16 GEMM: acc[MT][NT][4] += (Ahi+Alo) @ (Bhi+Blo)^T (3 combos)
// A: [m][k] padded rows LDA (bf16 elems); B: [n][k] padded rows LDB.
template<int MT, int NT, int KS, int LDA, int LDB>
__device__ __forceinline__ void warp_gemm3(
    uint32_t Ah, uint32_t Al, uint32_t Bh, uint32_t Bl,
    int mbase, int nbase, int lane, float (&acc)[MT][NT][4])
{
    const uint32_t dA = Al - Ah;
    const uint32_t dB = Bl - Bh;
    // per-mt A base address (lane pattern for ldmatrix x4 on m16k16)
    uint32_t aAddr[MT];
    #pragma unroll
    for (int mt = 0; mt < MT; mt++)
        aAddr[mt] = Ah + (uint32_t)(((mbase + mt * 16 + (lane & 15)) * LDA + (lane >> 4) * 8) * 2);
    // per-pair B base address (x4 loads 2 n-tiles: n8 each)
    uint32_t bAddr[NT / 2];
    #pragma unroll
    for (int p = 0; p < NT / 2; p++)
        bAddr[p] = Bh + (uint32_t)(((nbase + p * 16 + (lane >> 4) * 8 + (lane & 7)) * LDB
                                    + ((lane >> 3) & 1) * 8) * 2);

    #pragma unroll
    for (int ks = 0; ks < KS; ks++) {
        const uint32_t ko = ks * 32;   // 16 bf16 = 32 bytes
        uint32_t ah[MT][4], al[MT][4];
        #pragma unroll
        for (int mt = 0; mt < MT; mt++) {
            LDSM4(ah[mt][0], ah[mt][1], ah[mt][2], ah[mt][3], aAddr[mt] + ko);
            LDSM4(al[mt][0], al[mt][1], al[mt][2], al[mt][3], aAddr[mt] + ko + dA);
        }
        uint32_t bh[NT][2], bl[NT][2];
        #pragma unroll
        for (int p = 0; p < NT / 2; p++) {
            LDSM4(bh[2 * p][0], bh[2 * p][1], bh[2 * p + 1][0], bh[2 * p + 1][1], bAddr[p] + ko);
            LDSM4(bl[2 * p][0], bl[2 * p][1], bl[2 * p + 1][0], bl[2 * p + 1][1], bAddr[p] + ko + dB);
        }
        #pragma unroll
        for (int mt = 0; mt < MT; mt++)
            #pragma unroll
            for (int nt = 0; nt < NT; nt++) {
                mma16816(acc[mt][nt], ah[mt][0], ah[mt][1], ah[mt][2], ah[mt][3], bh[nt][0], bh[nt][1]);
                mma16816(acc[mt][nt], ah[mt][0], ah[mt][1], ah[mt][2], ah[mt][3], bl[nt][0], bl[nt][1]);
                mma16816(acc[mt][nt], al[mt][0], al[mt][1], al[mt][2], al[mt][3], bh[nt][0], bh[nt][1]);
            }
    }
}

// =====================================================================
// Phase 1: z = tanh(x @ Wx^T + b_x) @ Wih^T + b_ih        [R_TOT, 128]
// 256 threads (8 warps, 4m x 2n), 128 rows/CTA, HMMA split-bf16
// =====================================================================
#define LDA1 72     // 64 + 8 pad (bf16 elems)
#define LDW  136    // 128 + 8 pad
// byte offsets in dynamic smem
#define P1_A1H 0
#define P1_A1L 18432
#define P1_B1H 36864
#define P1_B1L 55296
#define P1_B2H 73728
#define P1_B2L 108544
#define P1_FH  143360
#define P1_FL  178176
#define P1_DYN 212992

__global__ __launch_bounds__(256) void phase1_mma(
    const float* __restrict__ x, const float* __restrict__ Wx,
    const float* __restrict__ Wih, const float* __restrict__ b_x,
    const float* __restrict__ b_ih)
{
    extern __shared__ __align__(16) unsigned char sm[];
    __shared__ float s_bx[128], s_bih[128];

    const int tid = threadIdx.x, lane = tid & 31, wid = tid >> 5;
    const int wm = wid >> 1, wn = wid & 1;
    const int row0 = blockIdx.x * 128;
    const uint32_t sb = smaddr(sm);

    if (tid < 128) { s_bx[tid] = b_x[tid]; s_bih[tid] = b_ih[tid]; }

    // Wx [128n][64k] -> split bf16, padded
    {
        const float2* w2 = (const float2*)Wx;
        for (int p = tid; p < 4096; p += 256) {
            int n = p >> 5, kp = (p & 31) * 2;
            float2 v = w2[p];
            uint32_t hi, lo; split2(v.x, v.y, hi, lo);
            *(uint32_t*)(sm + P1_B1H + (n * LDA1 + kp) * 2) = hi;
            *(uint32_t*)(sm + P1_B1L + (n * LDA1 + kp) * 2) = lo;
        }
    }
    // Wih [128n][128k]
    {
        const float2* w2 = (const float2*)Wih;
        for (int p = tid; p < 8192; p += 256) {
            int n = p >> 6, kp = (p & 63) * 2;
            float2 v = w2[p];
            uint32_t hi, lo; split2(v.x, v.y, hi, lo);
            *(uint32_t*)(sm + P1_B2H + (n * LDW + kp) * 2) = hi;
            *(uint32_t*)(sm + P1_B2L + (n * LDW + kp) * 2) = lo;
        }
    }
    // x tile [128m][64k]
    {
        const float2* xg = (const float2*)(x + (size_t)row0 * 64);
        for (int p = tid; p < 4096; p += 256) {
            int m = p >> 5, kp = (p & 31) * 2;
            float2 v = xg[p];
            uint32_t hi, lo; split2(v.x, v.y, hi, lo);
            *(uint32_t*)(sm + P1_A1H + (m * LDA1 + kp) * 2) = hi;
            *(uint32_t*)(sm + P1_A1L + (m * LDA1 + kp) * 2) = lo;
        }
    }
    __syncthreads();

    // GEMM1: [128,64] @ [128,64]^T -> [128,128]
    float acc[2][8][4];
    #pragma unroll
    for (int a = 0; a < 2; a++)
        #pragma unroll
        for (int b = 0; b < 8; b++)
            #pragma unroll
            for (int c = 0; c < 4; c++) acc[a][b][c] = 0.0f;

    warp_gemm3<2, 8, 4, LDA1, LDA1>(sb + P1_A1H, sb + P1_A1L, sb + P1_B1H, sb + P1_B1L,
                                    wm * 32, wn * 64, lane, acc);

    // Epilogue1: fs = tanh(acc + b_x) -> split bf16 smem
    #pragma unroll
    for (int mt = 0; mt < 2; mt++)
        #pragma unroll
        for (int nt = 0; nt < 8; nt++) {
            int row = wm * 32 + mt * 16 + (lane >> 2);
            int col = wn * 64 + nt * 8 + 2 * (lane & 3);
            float t0 = tanhf(acc[mt][nt][0] + s_bx[col]);
            float t1 = tanhf(acc[mt][nt][1] + s_bx[col + 1]);
            uint32_t hi, lo; split2(t0, t1, hi, lo);
            *(uint32_t*)(sm + P1_FH + (row * LDW + col) * 2) = hi;
            *(uint32_t*)(sm + P1_FL + (row * LDW + col) * 2) = lo;
            float t2 = tanhf(acc[mt][nt][2] + s_bx[col]);
            float t3 = tanhf(acc[mt][nt][3] + s_bx[col + 1]);
            split2(t2, t3, hi, lo);
            *(uint32_t*)(sm + P1_FH + ((row + 8) * LDW + col) * 2) = hi;
            *(uint32_t*)(sm + P1_FL + ((row + 8) * LDW + col) * 2) = lo;
        }
    __syncthreads();

    // GEMM2: fs[128,128] @ Wih[128,128]^T -> z
    #pragma unroll
    for (int a = 0; a < 2; a++)
        #pragma unroll
        for (int b = 0; b < 8; b++)
            #pragma unroll
            for (int c = 0; c < 4; c++) acc[a][b][c] = 0.0f;

    warp_gemm3<2, 8, 8, LDW, LDW>(sb + P1_FH, sb + P1_FL, sb + P1_B2H, sb + P1_B2L,
                                  wm * 32, wn * 64, lane, acc);

    // Epilogue2: z = acc + b_ih -> g_z
    #pragma unroll
    for (int mt = 0; mt < 2; mt++)
        #pragma unroll
        for (int nt = 0; nt < 8; nt++) {
            int row = row0 + wm * 32 + mt * 16 + (lane >> 2);
            int col = wn * 64 + nt * 8 + 2 * (lane & 3);
            float2 v0 = make_float2(acc[mt][nt][0] + s_bih[col], acc[mt][nt][1] + s_bih[col + 1]);
            float2 v1 = make_float2(acc[mt][nt][2] + s_bih[col], acc[mt][nt][3] + s_bih[col + 1]);
            *(float2*)(g_z + (size_t)row * 128 + col) = v0;
            *(float2*)(g_z + (size_t)(row + 8) * 128 + col) = v1;
        }
}

// =====================================================================
// Phase 3: y = tanh(h @ Wh^T + b_h) @ Wg^T + b_g          [R_TOT, 64]
// =====================================================================
#define P3_A1H 0
#define P3_A1L 34816
#define P3_B1H 69632
#define P3_B1L 104448
#define P3_B2H 139264
#define P3_B2L 156672
#define P3_DYN 174080

__global__ __launch_bounds__(256) void phase3_mma(
    const float* __restrict__ Wh, const float* __restrict__ Wg,
    const float* __restrict__ b_h, const float* __restrict__ b_g,
    float* __restrict__ y)
{
    extern __shared__ __align__(16) unsigned char sm[];
    __shared__ float s_bh[128], s_bg[64];

    const int tid = threadIdx.x, lane = tid & 31, wid = tid >> 5;
    const int wm = wid >> 1, wn = wid & 1;
    const int row0 = blockIdx.x * 128;
    const uint32_t sb = smaddr(sm);

    if (tid < 128) s_bh[tid] = b_h[tid];
    if (tid < 64)  s_bg[tid] = b_g[tid];

    // Wh [128n][128k]
    {
        const float2* w2 = (const float2*)Wh;
        for (int p = tid; p < 8192; p += 256) {
            int n = p >> 6, kp = (p & 63) * 2;
            float2 v = w2[p];
            uint32_t hi, lo; split2(v.x, v.y, hi, lo);
            *(uint32_t*)(sm + P3_B1H + (n * LDW + kp) * 2) = hi;
            *(uint32_t*)(sm + P3_B1L + (n * LDW + kp) * 2) = lo;
        }
    }
    // Wg [64n][128k]
    {
        const float2* w2 = (const float2*)Wg;
        for (int p = tid; p < 4096; p += 256) {
            int n = p >> 6, kp = (p & 63) * 2;
            float2 v = w2[p];
            uint32_t hi, lo; split2(v.x, v.y, hi, lo);
            *(uint32_t*)(sm + P3_B2H + (n * LDW + kp) * 2) = hi;
            *(uint32_t*)(sm + P3_B2L + (n * LDW + kp) * 2) = lo;
        }
    }
    // h tile [128m][128k]
    {
        const float2* hg = (const float2*)(g_h + (size_t)row0 * 128);
        for (int p = tid; p < 8192; p += 256) {
            int m = p >> 6, kp = (p & 63) * 2;
            float2 v = hg[p];
            uint32_t hi, lo; split2(v.x, v.y, hi, lo);
            *(uint32_t*)(sm + P3_A1H + (m * LDW + kp) * 2) = hi;
            *(uint32_t*)(sm + P3_A1L + (m * LDW + kp) * 2) = lo;
        }
    }
    __syncthreads();

    // GEMM1: h @ Wh^T -> [128,128]
    float acc[2][8][4];
    #pragma unroll
    for (int a = 0; a < 2; a++)
        #pragma unroll
        for (int b = 0; b < 8; b++)
            #pragma unroll
            for (int c = 0; c < 4; c++) acc[a][b][c] = 0.0f;

    warp_gemm3<2, 8, 8, LDW, LDW>(sb + P3_A1H, sb + P3_A1L, sb + P3_B1H, sb + P3_B1L,
                                  wm * 32, wn * 64, lane, acc);
    __syncthreads();   // everyone done reading A1 before overwrite

    // Epilogue1: u = tanh(acc + b_h) -> overwrite A1 buffers
    #pragma unroll
    for (int mt = 0; mt < 2; mt++)
        #pragma unroll
        for (int nt = 0; nt < 8; nt++) {
            int row = wm * 32 + mt * 16 + (lane >> 2);
            int col = wn * 64 + nt * 8 + 2 * (lane & 3);
            float t0 = tanhf(acc[mt][nt][0] + s_bh[col]);
            float t1 = tanhf(acc[mt][nt][1] + s_bh[col + 1]);
            uint32_t hi, lo; split2(t0, t1, hi, lo);
            *(uint32_t*)(sm + P3_A1H + (row * LDW + col) * 2) = hi;
            *(uint32_t*)(sm + P3_A1L + (row * LDW + col) * 2) = lo;
            float t2 = tanhf(acc[mt][nt][2] + s_bh[col]);
            float t3 = tanhf(acc[mt][nt][3] + s_bh[col + 1]);
            split2(t2, t3, hi, lo);
            *(uint32_t*)(sm + P3_A1H + ((row + 8) * LDW + col) * 2) = hi;
            *(uint32_t*)(sm + P3_A1L + ((row + 8) * LDW + col) * 2) = lo;
        }
    __syncthreads();

    // GEMM2: u[128,128] @ Wg[64,128]^T -> [128,64]; warps: 4m x 2n (n32 each)
    float ac2[2][4][4];
    #pragma unroll
    for (int a = 0; a < 2; a++)
        #pragma unroll
        for (int b = 0; b < 4; b++)
            #pragma unroll
            for (int c = 0; c < 4; c++) ac2[a][b][c] = 0.0f;

    warp_gemm3<2, 4, 8, LDW, LDW>(sb + P3_A1H, sb + P3_A1L, sb + P3_B2H, sb + P3_B2L,
                                  wm * 32, wn * 32, lane, ac2);

    // Epilogue2: y = acc + b_g
    #pragma unroll
    for (int mt = 0; mt < 2; mt++)
        #pragma unroll
        for (int nt = 0; nt < 4; nt++) {
            int row = row0 + wm * 32 + mt * 16 + (lane >> 2);
            int col = wn * 32 + nt * 8 + 2 * (lane & 3);
            float2 v0 = make_float2(ac2[mt][nt][0] + s_bg[col], ac2[mt][nt][1] + s_bg[col + 1]);
            float2 v1 = make_float2(ac2[mt][nt][2] + s_bg[col], ac2[mt][nt][3] + s_bg[col + 1]);
            *(float2*)(y + (size_t)row * 64 + col) = v0;
            *(float2*)(y + (size_t)(row + 8) * 64 + col) = v1;
        }
}

// =====================================================================
// Phase 2: recurrence (round-1 measured-good version, unchanged)
// =====================================================================
__device__ __forceinline__ ull pk2(float lo, float hi) {
    ull r;
    asm("mov.b64 %0, {%1,%2};" : "=l"(r) : "r"(__float_as_uint(lo)), "r"(__float_as_uint(hi)));
    return r;
}
__device__ __forceinline__ float2 upk2(ull v) {
    unsigned int lo, hi;
    asm("mov.b64 {%0,%1}, %2;" : "=r"(lo), "=r"(hi) : "l"(v));
    return make_float2(__uint_as_float(lo), __uint_as_float(hi));
}
__device__ __forceinline__ void fma2(ull& d, ull a, ull b) {
    asm("fma.rn.f32x2 %0, %1, %2, %0;" : "+l"(d) : "l"(a), "l"(b));
}

__global__ __launch_bounds__(128, 3) void rnn_kernel(
    const float* __restrict__ W_hh, const float* __restrict__ b_hh)
{
    __shared__ __align__(16) float hs[128];

    const int b = blockIdx.x;
    const int j = threadIdx.x;

    ull w[64];
    const ulonglong2* w2 = (const ulonglong2*)(W_hh + j * 128);
    #pragma unroll
    for (int i = 0; i < 32; i++) {
        ulonglong2 v = w2[i];
        w[2 * i]     = v.x;
        w[2 * i + 1] = v.y;
    }
    const float bh = b_hh[j];

    hs[j] = 0.0f;
    g_h[(size_t)b * 128 + j] = 0.0f;                 // h_0 = 0
    float zreg = g_z[(size_t)b * 128 + j];           // z_0
    __syncthreads();

    for (int t = 0; t < T_LEN - 1; ++t) {
        float znext = 0.0f;
        if (t < T_LEN - 2) znext = g_z[(size_t)(t + 1) * BH + b * 128 + j];

        ull a0 = 0, a1 = 0, a2 = 0, a3 = 0;
        const ulonglong2* h2 = (const ulonglong2*)hs;
        #pragma unroll
        for (int i = 0; i < 16; i++) {
            ulonglong2 hv = h2[i];
            fma2(a0, hv.x, w[2 * i]);
            fma2(a1, hv.y, w[2 * i + 1]);
        }
        #pragma unroll
        for (int i = 16; i < 32; i++) {
            ulonglong2 hv = h2[i];
            fma2(a2, hv.x, w[2 * i]);
            fma2(a3, hv.y, w[2 * i + 1]);
        }
        float2 f0 = upk2(a0), f1 = upk2(a1), f2 = upk2(a2), f3 = upk2(a3);
        float s = ((f0.x + f0.y) + (f1.x + f1.y)) + ((f2.x + f2.y) + (f3.x + f3.y));
        float hn = tanhf(s + zreg + bh);

        __syncthreads();                 // all reads of hs done
        hs[j] = hn;
        g_h[(size_t)(t + 1) * BH + b * 128 + j] = hn;
        zreg = znext;
        __syncthreads();                 // new hs visible
    }
}

// =====================================================================
extern "C" void kernel_launch(void* const* d_in, const int* in_sizes, int n_in,
                              void* d_out, int out_size)
{
    const float* x    = (const float*)d_in[0];
    const float* W_x  = (const float*)d_in[1];
    const float* b_x  = (const float*)d_in[2];
    const float* W_ih = (const float*)d_in[3];
    const float* b_ih = (const float*)d_in[4];
    const float* W_hh = (const float*)d_in[5];
    const float* b_hh = (const float*)d_in[6];
    const float* W_h  = (const float*)d_in[7];
    const float* b_h  = (const float*)d_in[8];
    const float* W_g  = (const float*)d_in[9];
    const float* b_g  = (const float*)d_in[10];
    float* y = (float*)d_out;

    cudaFuncSetAttribute(phase1_mma, cudaFuncAttributeMaxDynamicSharedMemorySize, P1_DYN);
    cudaFuncSetAttribute(phase3_mma, cudaFuncAttributeMaxDynamicSharedMemorySize, P3_DYN);

    phase1_mma<<<R_TOT / 128, 256, P1_DYN>>>(x, W_x, W_ih, b_x, b_ih);
    rnn_kernel<<<B_DIM, 128>>>(W_hh, b_hh);
    phase3_mma<<<R_TOT / 128, 256, P3_DYN>>>(W_h, W_g, b_h, b_g, y);
}